// round 17
// baseline (speedup 1.0000x reference)
#include <cuda_runtime.h>

// BSplineLayer: piecewise-linear spline eval.
// u: [4096, 64, 256] f32 (flat, channel = i % 256)
// knots: [256, 64] sorted ascending per channel; coefs: [256, 64].
// out = c0 + (x-k0)/(k1-k0+1e-6) * (c1-c0), segment via searchsorted-left.
//
// TERMINAL FORM (session: 297.5 -> 96.8 us, 3.07x). Stability confirmed
// across two identical-source runs (98.2 / 96.8 bench; ncu 98.3 / 98.2).
// Measured: 1072 MB compulsory combined L2 traffic / 98.2us ncu = 10.9 TB/s
// = the sm_103a path-independent LTS chip cap (6100-6300 B/cyc band).
// All SM-local pipes have slack (DRAM 62%, L1 61%, issue 26%); all
// structural levers tested and closed: LDS conflicts (R9: flat), per-warp
// MLP (R10: flat), warp count (R5-R7: worse), icount (R11: flat),
// prologue (R12/13/15: -6us), streaming hints (R14: -1.4us). Both byte
// streams are compulsory; this is the roofline.
//
// Structure: conflict-free permuted fp32 table sseg[(j<<8)+COLP(c)]
// (LDS.64 bank-pair = 2*lane, independent of data-dependent j), 1024x1
// CTA/SM, 8 consecutive elements per thread via 2 front-batched LDG.128
// with __ldcs/__stcs streaming, per-channel affine params in registers;
// exact binary-search fallback if knots are not affine.

#define M_CH    256
#define K_KNOTS 64
#define N_SEG   63
#define EPS     1e-6f

#define COLP(c) (((c) >> 3) + (((c) & 7) << 5))

// smem: float2 sparam[256] (invh,b) | float sscale[256] | float2 sseg[64*256] | int flag
#define SMEM_BYTES (256 * 8 + 256 * 4 + 64 * 256 * 8 + 16)

__global__ __launch_bounds__(1024, 1)
void bspline_kernel(const float* __restrict__ u,
                    const float* __restrict__ knots,
                    const float* __restrict__ coefs,
                    float* __restrict__ out,
                    int n8 /* groups of 8 elements */)
{
    extern __shared__ char smem_raw[];
    float2* sparam = (float2*)smem_raw;                          // [256] (invh, b)
    float*  sscale = (float*)(smem_raw + 256 * 8);               // [256] scale
    float2* sseg   = (float2*)(smem_raw + 256 * 8 + 256 * 4);    // [64][256] permuted
    int*    sflag  = (int*)(smem_raw + 256 * 8 + 256 * 4 + 64 * 256 * 8);

    const int tid = threadIdx.x;

    if (tid == 0) *sflag = 0;
    __syncthreads();

    // ---- fused staging + fully parallel uniformity check ----
    // one work-item per (c, j): stage sseg[(j<<8)+COLP(c)] and verify
    // knots[c,j] against the channel's affine prediction. All loads issued
    // independently up front -> two latency rounds total.
    bool bad = false;
    for (int i = tid; i < M_CH * K_KNOTS; i += blockDim.x) {
        int c = i >> 6;
        int j = i & 63;
        float kj = __ldg(knots + i);
        float k0 = __ldg(knots + c * K_KNOTS);
        float kl = __ldg(knots + c * K_KNOTS + K_KNOTS - 1);
        float c0 = __ldg(coefs + c * K_KNOTS + j);
        float c1 = __ldg(coefs + c * K_KNOTS + min(j + 1, K_KNOTS - 1));
        float h  = (kl - k0) * (1.0f / (float)N_SEG);
        float tol = 1e-4f * fabsf(h) + 1e-30f;
        float pred = fmaf((float)j, h, k0);
        if (!(h > 0.0f) || fabsf(kj - pred) > tol) bad = true;
        if (j < N_SEG)
            sseg[(j << 8) + COLP(c)] = make_float2(c0, c1 - c0);
        if (j == 0) {  // one writer per channel; reuses k0/kl already in regs
            float invh = (float)N_SEG / (kl - k0);
            sparam[c] = make_float2(invh, -k0 * invh);
            sscale[c] = h / (h + EPS);
        }
    }
    if (bad) *sflag = 1;       // only 1s written after the 0-init barrier
    __syncthreads();

    const bool affine = (*sflag == 0);

    const float4* __restrict__ u4 = (const float4*)u;
    float4*       __restrict__ o4 = (float4*)out;
    const int gtid   = blockIdx.x * blockDim.x + tid;
    const int stride = blockDim.x * gridDim.x;   // group stride; 8*stride % 256 == 0
    const int cb     = (gtid * 8) & (M_CH - 1);  // channels cb..cb+7, fixed

    if (affine) {
        // preload this thread's 8 channel params into registers
        float p_invh[8], p_b[8], p_scale[8];
        #pragma unroll
        for (int i = 0; i < 8; i++) {
            float2 p = sparam[cb + i];
            p_invh[i] = p.x; p_b[i] = p.y;
            p_scale[i] = sscale[cb + i];
        }
        // permuted table base: + (i<<5) + (j<<8) per access; bank-pair = 2*lane
        const float2* __restrict__ seg0 = sseg + (cb >> 3);

        for (int t = gtid; t < n8; t += stride) {
            float4 a = __ldcs(u4 + 2 * t);        // streaming: read-once data
            float4 b = __ldcs(u4 + 2 * t + 1);
            float x[8] = {a.x, a.y, a.z, a.w, b.x, b.y, b.z, b.w};
            float r[8];
            #pragma unroll
            for (int i = 0; i < 8; i++) {
                float s  = fmaf(x[i], p_invh[i], p_b[i]);
                float jf = floorf(s);
                jf = fminf(fmaxf(jf, 0.0f), (float)(N_SEG - 1));
                int  ji = (int)jf;
                float2 cd = seg0[(ji << 8) + (i << 5)];   // conflict-free LDS.64
                float tt = (s - jf) * p_scale[i];
                r[i] = fmaf(tt, cd.y, cd.x);
            }
            __stcs(o4 + 2 * t,     make_float4(r[0], r[1], r[2], r[3]));
            __stcs(o4 + 2 * t + 1, make_float4(r[4], r[5], r[6], r[7]));
        }
    } else {
        // generic fallback: exact searchsorted-left via binary search, f32 math
        for (int t = gtid; t < n8; t += stride) {
            float4 a = u4[2 * t];
            float4 b = u4[2 * t + 1];
            float x[8] = {a.x, a.y, a.z, a.w, b.x, b.y, b.z, b.w};
            float r[8];
            #pragma unroll
            for (int i = 0; i < 8; i++) {
                const int c = cb + i;
                const float* kc = knots + c * K_KNOTS;
                const float xi = x[i];
                int lo = 0, hi = K_KNOTS;
                while (lo < hi) {
                    int mid = (lo + hi) >> 1;
                    if (__ldg(kc + mid) < xi) lo = mid + 1; else hi = mid;
                }
                int j = min(max(lo - 1, 0), N_SEG - 1);
                float k0 = __ldg(kc + j);
                float k1 = __ldg(kc + j + 1);
                float2 cd = sseg[(j << 8) + COLP(c)];
                float tt = (xi - k0) / (k1 - k0 + EPS);
                r[i] = fmaf(tt, cd.y, cd.x);
            }
            o4[2 * t]     = make_float4(r[0], r[1], r[2], r[3]);
            o4[2 * t + 1] = make_float4(r[4], r[5], r[6], r[7]);
        }
    }
}

extern "C" void kernel_launch(void* const* d_in, const int* in_sizes, int n_in,
                              void* d_out, int out_size)
{
    const float* u     = (const float*)d_in[0];
    const float* knots = (const float*)d_in[1];
    const float* coefs = (const float*)d_in[2];
    float*       out   = (float*)d_out;

    const int n  = in_sizes[0];   // 67,108,864 (divisible by 8)
    const int n8 = n >> 3;

    static_assert(SMEM_BYTES <= 227 * 1024, "smem over sm_103a limit");
    cudaFuncSetAttribute(bspline_kernel,
                         cudaFuncAttributeMaxDynamicSharedMemorySize, SMEM_BYTES);

    int dev = 0, nsm = 148;
    cudaGetDevice(&dev);
    cudaDeviceGetAttribute(&nsm, cudaDevAttrMultiProcessorCount, dev);

    bspline_kernel<<<nsm, 1024, SMEM_BYTES>>>(u, knots, coefs, out, n8);
}